// round 1
// baseline (speedup 1.0000x reference)
#include <cuda_runtime.h>
#include <cuda_bf16.h>

#define H        4096
#define T_TRAIN  2048
#define GRID     148
#define BLOCK    1024
#define HMAX     64

// ---------------- persistent device state (reset each launch via memsets) ---
__device__ float    g_h[2][H];                 // ping-pong hidden state
__device__ float    g_vhp[HMAX + 1][GRID];     // per-CTA partials of v . h_new
__device__ unsigned g_count;                   // barrier arrival counter
__device__ unsigned g_phase;                   // barrier phase (monotone)

// ---------------- grid-wide barrier (single co-resident wave) ---------------
__device__ __forceinline__ void grid_barrier(unsigned &local_phase, int G) {
    __threadfence();
    __syncthreads();
    if (threadIdx.x == 0) {
        unsigned target = local_phase + 1;
        unsigned arrived = atomicAdd(&g_count, 1u) + 1;
        if (arrived == (unsigned)G) {
            atomicExch(&g_count, 0u);
            __threadfence();
            atomicAdd(&g_phase, 1u);
        } else {
            volatile unsigned* ph = &g_phase;
            while (*ph < target) { }
        }
    }
    local_phase++;
    __syncthreads();
    __threadfence();
}

__device__ __forceinline__ float sigmoidf_fast(float z) {
    return 1.0f / (1.0f + __expf(-z));
}

// ---------------- persistent GRU kernel -------------------------------------
__global__ void __launch_bounds__(BLOCK, 1)
gru_persistent(const float* __restrict__ x_seq,
               const float* __restrict__ uwx, const float* __restrict__ uWh,
               const float* __restrict__ ub,
               const float* __restrict__ rwx, const float* __restrict__ rWh,
               const float* __restrict__ rb,
               const float* __restrict__ wx,  const float* __restrict__ Wh,
               const float* __restrict__ bb,
               const float* __restrict__ v,   const float* __restrict__ cc,
               float* __restrict__ out, int horizon)
{
    __shared__ float h_s[H];
    __shared__ float au_s[32], ar_s[32], aw_s[32];
    __shared__ float red_s[32];
    __shared__ float x_s;

    const int tid  = threadIdx.x;
    const int b    = blockIdx.x;
    const int G    = gridDim.x;
    const int warp = tid >> 5;
    const int lane = tid & 31;

    // contiguous row ownership
    const int r0 = (int)(((long long)b       * H) / G);
    const int r1 = (int)(((long long)(b + 1) * H) / G);
    const int nrows = r1 - r0;

    const float c0 = cc[0];
    unsigned phase = 0;
    const int total_steps = T_TRAIN + horizon;

    for (int t = 0; t < total_steps; ++t) {
        const int par = t & 1;
        const float* hin  = g_h[par];
        float*       hout = g_h[par ^ 1];

        // x for this step (deterministic: thread 0 re-sums the partials)
        if (tid == 0) {
            float x;
            if (t < T_TRAIN) {
                x = x_seq[t];
            } else {
                const float* p = g_vhp[t - T_TRAIN];
                float s = 0.f;
                for (int i = 0; i < G; ++i) s += p[i];
                x = s + c0;
            }
            x_s = x;
        }

        // stage h into SMEM
        {
            const float4* hin4 = (const float4*)hin;
            float4*       hs4  = (float4*)h_s;
            for (int i = tid; i < H / 4; i += BLOCK) hs4[i] = hin4[i];
        }
        __syncthreads();
        const float x = x_s;

        // three matvecs for owned rows: warp-per-(row,matrix) task
        const int ntasks = nrows * 3;
        for (int task = warp; task < ntasks; task += (BLOCK / 32)) {
            const int lr = task / 3;
            const int m  = task - lr * 3;   // 0=u, 1=r, 2=candidate
            const int row = r0 + lr;
            const float* Wrow = (m == 0 ? uWh : (m == 1 ? rWh : Wh)) + (size_t)row * H;
            const float4* W4 = (const float4*)Wrow;
            const float4* h4 = (const float4*)h_s;
            float sum = 0.f;
            #pragma unroll 8
            for (int i = lane; i < H / 4; i += 32) {
                const float4 w  = W4[i];
                const float4 hh = h4[i];
                sum += w.x * hh.x + w.y * hh.y + w.z * hh.z + w.w * hh.w;
            }
            #pragma unroll
            for (int o = 16; o; o >>= 1) sum += __shfl_down_sync(0xffffffffu, sum, o);
            if (lane == 0) {
                (m == 0 ? au_s : (m == 1 ? ar_s : aw_s))[lr] = sum;
            }
        }
        __syncthreads();

        // gate math + h update for owned rows
        const bool need_y = (t >= T_TRAIN - 1);
        if (tid < nrows) {
            const int row = r0 + tid;
            const float h_old = h_s[row];
            const float u  = sigmoidf_fast(uwx[row] * x + au_s[tid] + ub[row]);
            const float r  = sigmoidf_fast(rwx[row] * x + ar_s[tid] + rb[row]);
            const float hh = tanhf(wx[row] * x + r * aw_s[tid] + bb[row]);
            const float hn = h_old + u * (hh - h_old);
            hout[row] = hn;
            red_s[tid] = need_y ? v[row] * hn : 0.f;
        }
        __syncthreads();
        if (need_y && tid == 0) {
            float s = 0.f;
            for (int i = 0; i < nrows; ++i) s += red_s[i];
            g_vhp[t - (T_TRAIN - 1)][b] = s;
        }

        grid_barrier(phase, G);
    }

    // emit predictions (deterministic final reduction)
    if (b == 0 && tid < horizon) {
        const float* p = g_vhp[tid + 1];
        float s = 0.f;
        for (int i = 0; i < G; ++i) s += p[i];
        out[tid] = s + c0;
    }
}

// ---------------- launch ----------------------------------------------------
extern "C" void kernel_launch(void* const* d_in, const int* in_sizes, int n_in,
                              void* d_out, int out_size)
{
    (void)in_sizes; (void)n_in;
    const float* x_seq = (const float*)d_in[0];
    // d_in[1] is the scalar 'horizon' (int32); we use out_size instead.
    const float* uwx = (const float*)d_in[2];
    const float* uWh = (const float*)d_in[3];
    const float* ub  = (const float*)d_in[4];
    const float* rwx = (const float*)d_in[5];
    const float* rWh = (const float*)d_in[6];
    const float* rb  = (const float*)d_in[7];
    const float* wx  = (const float*)d_in[8];
    const float* Wh  = (const float*)d_in[9];
    const float* bb  = (const float*)d_in[10];
    const float* v   = (const float*)d_in[11];
    const float* cc  = (const float*)d_in[12];

    int horizon = out_size;
    if (horizon > HMAX) horizon = HMAX;

    // reset persistent state (graph-capturable, deterministic per replay)
    void* p;
    cudaGetSymbolAddress(&p, g_h);     cudaMemsetAsync(p, 0, sizeof(float) * 2 * H);
    cudaGetSymbolAddress(&p, g_count); cudaMemsetAsync(p, 0, sizeof(unsigned));
    cudaGetSymbolAddress(&p, g_phase); cudaMemsetAsync(p, 0, sizeof(unsigned));

    gru_persistent<<<GRID, BLOCK>>>(x_seq,
                                    uwx, uWh, ub,
                                    rwx, rWh, rb,
                                    wx,  Wh,  bb,
                                    v,   cc,
                                    (float*)d_out, horizon);
}

// round 2
// speedup vs baseline: 2.6787x; 2.6787x over previous
#include <cuda_runtime.h>
#include <cuda_fp16.h>

#define H        4096
#define T_TRAIN  2048
#define GRID     148
#define BLOCK    1024
#define HMAX     64

// ---------------- persistent device state ----------------------------------
__device__ __half   g_wu[(size_t)H * H];       // fp16 copies of the 3 weight mats
__device__ __half   g_wr[(size_t)H * H];
__device__ __half   g_wc[(size_t)H * H];
__device__ float    g_h[2][H];                 // ping-pong hidden state
__device__ float    g_vhp[HMAX + 1][GRID];     // per-CTA partials of v . h_new
__device__ unsigned g_count;                   // barrier arrival counter
__device__ unsigned g_phase;                   // barrier phase (monotone)

// ---------------- one-time fp32 -> fp16 weight conversion -------------------
__global__ void convert_w(const float* __restrict__ u,
                          const float* __restrict__ r,
                          const float* __restrict__ c)
{
    const int n4 = (H * H) / 4;
    int i = blockIdx.x * blockDim.x + threadIdx.x;
    if (i >= n4) return;
    float4 a = ((const float4*)u)[i];
    float4 b = ((const float4*)r)[i];
    float4 d = ((const float4*)c)[i];
    __half2* pu = (__half2*)g_wu;
    __half2* pr = (__half2*)g_wr;
    __half2* pc = (__half2*)g_wc;
    pu[2 * i]     = __floats2half2_rn(a.x, a.y);
    pu[2 * i + 1] = __floats2half2_rn(a.z, a.w);
    pr[2 * i]     = __floats2half2_rn(b.x, b.y);
    pr[2 * i + 1] = __floats2half2_rn(b.z, b.w);
    pc[2 * i]     = __floats2half2_rn(d.x, d.y);
    pc[2 * i + 1] = __floats2half2_rn(d.z, d.w);
}

// ---------------- grid-wide barrier (single co-resident wave) ---------------
__device__ __forceinline__ void grid_barrier(unsigned &local_phase, int G) {
    __threadfence();
    __syncthreads();
    if (threadIdx.x == 0) {
        unsigned target = local_phase + 1;
        unsigned arrived = atomicAdd(&g_count, 1u) + 1;
        if (arrived == (unsigned)G) {
            atomicExch(&g_count, 0u);
            __threadfence();
            atomicAdd(&g_phase, 1u);
        } else {
            volatile unsigned* ph = &g_phase;
            while (*ph < target) { }
        }
    }
    local_phase++;
    __syncthreads();
    __threadfence();
}

__device__ __forceinline__ float sigmoidf_fast(float z) {
    return 1.0f / (1.0f + __expf(-z));
}

// ---------------- persistent GRU kernel -------------------------------------
__global__ void __launch_bounds__(BLOCK, 1)
gru_persistent(const float* __restrict__ x_seq,
               const float* __restrict__ uwx, const float* __restrict__ ub,
               const float* __restrict__ rwx, const float* __restrict__ rb,
               const float* __restrict__ wx,  const float* __restrict__ bb,
               const float* __restrict__ v,   const float* __restrict__ cc,
               float* __restrict__ out, int horizon)
{
    __shared__ float h_s[H];
    __shared__ float au_s[32], ar_s[32], aw_s[32];
    __shared__ float red_s[32];
    __shared__ float x_s;

    const int tid  = threadIdx.x;
    const int b    = blockIdx.x;
    const int G    = gridDim.x;
    const int warp = tid >> 5;
    const int lane = tid & 31;

    // contiguous row ownership
    const int r0 = (int)(((long long)b       * H) / G);
    const int r1 = (int)(((long long)(b + 1) * H) / G);
    const int nrows = r1 - r0;   // 27 or 28 (< 32)

    // hoisted per-row constants (gate math: thread tid owns row r0+tid)
    float p_uwx = 0.f, p_ub = 0.f, p_rwx = 0.f, p_rb = 0.f;
    float p_wx = 0.f, p_bb = 0.f, p_v = 0.f;
    if (tid < nrows) {
        const int row = r0 + tid;
        p_uwx = uwx[row]; p_ub = ub[row];
        p_rwx = rwx[row]; p_rb = rb[row];
        p_wx  = wx[row];  p_bb = bb[row];
        p_v   = v[row];
    }

    // matvec row pointers (warp w owns row r0+w, all three matrices)
    const uint2* WU = nullptr; const uint2* WR = nullptr; const uint2* WC = nullptr;
    const bool mv_active = (warp < nrows);
    if (mv_active) {
        const size_t off = (size_t)(r0 + warp) * H;
        WU = (const uint2*)(g_wu + off);
        WR = (const uint2*)(g_wr + off);
        WC = (const uint2*)(g_wc + off);
    }

    const float c0 = cc[0];
    unsigned phase = 0;
    const int total_steps = T_TRAIN + horizon;

    for (int t = 0; t < total_steps; ++t) {
        const int par = t & 1;
        const float* hin  = g_h[par];
        float*       hout = g_h[par ^ 1];

        // x for this step (deterministic: thread 0 re-sums partials)
        if (tid == 0) {
            float x;
            if (t < T_TRAIN) {
                x = x_seq[t];
            } else {
                const float* p = g_vhp[t - T_TRAIN];
                float s = 0.f;
                for (int i = 0; i < G; ++i) s += p[i];
                x = s + c0;
            }
            x_s = x;
        }

        // stage h into SMEM (1024 threads x 1 float4)
        {
            const float4* hin4 = (const float4*)hin;
            float4*       hs4  = (float4*)h_s;
            #pragma unroll
            for (int i = tid; i < H / 4; i += BLOCK) hs4[i] = hin4[i];
        }
        __syncthreads();
        const float x = x_s;

        // three fused matvecs: warp w -> row r0+w, 3 accumulators
        if (mv_active) {
            const float4* h4 = (const float4*)h_s;
            float su = 0.f, sr = 0.f, sc = 0.f;
            #pragma unroll 4
            for (int i = lane; i < H / 4; i += 32) {
                const uint2 au = WU[i];
                const uint2 ar = WR[i];
                const uint2 ac = WC[i];
                const float4 hh = h4[i];
                float2 u0 = __half22float2(*(const __half2*)&au.x);
                float2 u1 = __half22float2(*(const __half2*)&au.y);
                float2 r0f = __half22float2(*(const __half2*)&ar.x);
                float2 r1f = __half22float2(*(const __half2*)&ar.y);
                float2 c0f = __half22float2(*(const __half2*)&ac.x);
                float2 c1f = __half22float2(*(const __half2*)&ac.y);
                su += u0.x * hh.x + u0.y * hh.y + u1.x * hh.z + u1.y * hh.w;
                sr += r0f.x * hh.x + r0f.y * hh.y + r1f.x * hh.z + r1f.y * hh.w;
                sc += c0f.x * hh.x + c0f.y * hh.y + c1f.x * hh.z + c1f.y * hh.w;
            }
            #pragma unroll
            for (int o = 16; o; o >>= 1) {
                su += __shfl_down_sync(0xffffffffu, su, o);
                sr += __shfl_down_sync(0xffffffffu, sr, o);
                sc += __shfl_down_sync(0xffffffffu, sc, o);
            }
            if (lane == 0) { au_s[warp] = su; ar_s[warp] = sr; aw_s[warp] = sc; }
        }
        __syncthreads();

        // gate math + h update for owned rows
        const bool need_y = (t >= T_TRAIN - 1);
        if (tid < nrows) {
            const int row = r0 + tid;
            const float h_old = h_s[row];
            const float u  = sigmoidf_fast(p_uwx * x + au_s[tid] + p_ub);
            const float r  = sigmoidf_fast(p_rwx * x + ar_s[tid] + p_rb);
            const float hh = tanhf(p_wx * x + r * aw_s[tid] + p_bb);
            const float hn = h_old + u * (hh - h_old);
            hout[row] = hn;
            red_s[tid] = need_y ? p_v * hn : 0.f;
        }
        __syncthreads();
        if (need_y && tid == 0) {
            float s = 0.f;
            for (int i = 0; i < nrows; ++i) s += red_s[i];
            g_vhp[t - (T_TRAIN - 1)][b] = s;
        }

        grid_barrier(phase, G);
    }

    // emit predictions (deterministic final reduction)
    if (b == 0 && tid < horizon) {
        const float* p = g_vhp[tid + 1];
        float s = 0.f;
        for (int i = 0; i < G; ++i) s += p[i];
        out[tid] = s + c0;
    }
}

// ---------------- launch ----------------------------------------------------
extern "C" void kernel_launch(void* const* d_in, const int* in_sizes, int n_in,
                              void* d_out, int out_size)
{
    (void)in_sizes; (void)n_in;
    const float* x_seq = (const float*)d_in[0];
    // d_in[1] is the scalar 'horizon' (int32); we use out_size instead.
    const float* uwx = (const float*)d_in[2];
    const float* uWh = (const float*)d_in[3];
    const float* ub  = (const float*)d_in[4];
    const float* rwx = (const float*)d_in[5];
    const float* rWh = (const float*)d_in[6];
    const float* rb  = (const float*)d_in[7];
    const float* wx  = (const float*)d_in[8];
    const float* Wh  = (const float*)d_in[9];
    const float* bb  = (const float*)d_in[10];
    const float* v   = (const float*)d_in[11];
    const float* cc  = (const float*)d_in[12];

    int horizon = out_size;
    if (horizon > HMAX) horizon = HMAX;

    // reset persistent state (graph-capturable, deterministic per replay)
    void* p;
    cudaGetSymbolAddress(&p, g_h);     cudaMemsetAsync(p, 0, sizeof(float) * 2 * H);
    cudaGetSymbolAddress(&p, g_count); cudaMemsetAsync(p, 0, sizeof(unsigned));
    cudaGetSymbolAddress(&p, g_phase); cudaMemsetAsync(p, 0, sizeof(unsigned));

    // fp32 -> fp16 weight conversion (cheap; included every replay)
    {
        const int n4 = (H * H) / 4;
        convert_w<<<(n4 + 255) / 256, 256>>>(uWh, rWh, Wh);
    }

    gru_persistent<<<GRID, BLOCK>>>(x_seq,
                                    uwx, ub,
                                    rwx, rb,
                                    wx,  bb,
                                    v,   cc,
                                    (float*)d_out, horizon);
}

// round 5
// speedup vs baseline: 3.9855x; 1.4878x over previous
#include <cuda_runtime.h>
#include <cuda_fp16.h>

#define H        4096
#define T_TRAIN  2048
#define GRID     148
#define BLOCK    1024
#define HMAX     64
#define NCACHE   25          // U-matrix rows cached in SMEM per CTA (big-smem path)
#define ROW_U4   512         // uint4 per weight row (4096 halves = 8 KB)

// ---------------- persistent device state ----------------------------------
__device__ __half   g_wu[(size_t)H * H];   // fp16 weights, PERMUTED layout:
__device__ __half   g_wr[(size_t)H * H];   // row-chunk j = cols {4j..4j+3, 2048+4j..2048+4j+3}
__device__ __half   g_wc[(size_t)H * H];
__device__ float    g_h[2][H];
__device__ float    g_vhp[HMAX + 1][GRID];
__device__ unsigned g_count;
__device__ unsigned g_phase;

// ---------------- fp32 -> fp16 conversion with column permutation -----------
__global__ void convert_w(const float* __restrict__ u,
                          const float* __restrict__ r,
                          const float* __restrict__ c)
{
    const int total = H * ROW_U4;
    int idx = blockIdx.x * blockDim.x + threadIdx.x;
    if (idx >= total) return;
    const int row = idx >> 9;
    const int j   = idx & 511;
    const int i0  = row * (H / 4) + j;        // float4 index of cols 4j..4j+3
    const int i1  = i0 + 512;                 // float4 index of cols 2048+4j..+3

    #define CVT_ONE(SRC, DST)                                           \
    {                                                                   \
        float4 a = ((const float4*)SRC)[i0];                            \
        float4 b = ((const float4*)SRC)[i1];                            \
        uint4 o;                                                        \
        __half2 t;                                                      \
        t = __floats2half2_rn(a.x, a.y); o.x = *(unsigned*)&t;          \
        t = __floats2half2_rn(a.z, a.w); o.y = *(unsigned*)&t;          \
        t = __floats2half2_rn(b.x, b.y); o.z = *(unsigned*)&t;          \
        t = __floats2half2_rn(b.z, b.w); o.w = *(unsigned*)&t;          \
        ((uint4*)DST)[idx] = o;                                         \
    }
    CVT_ONE(u, g_wu)
    CVT_ONE(r, g_wr)
    CVT_ONE(c, g_wc)
    #undef CVT_ONE
}

// ---------------- grid-wide barrier (single co-resident wave) ---------------
__device__ __forceinline__ void grid_barrier(unsigned &local_phase, int G) {
    __threadfence();
    __syncthreads();
    if (threadIdx.x == 0) {
        unsigned target = local_phase + 1;
        unsigned arrived = atomicAdd(&g_count, 1u) + 1;
        if (arrived == (unsigned)G) {
            atomicExch(&g_count, 0u);
            __threadfence();
            atomicAdd(&g_phase, 1u);
        } else {
            volatile unsigned* ph = &g_phase;
            while (*ph < target) { }
        }
    }
    local_phase++;
    __syncthreads();
    __threadfence();
}

__device__ __forceinline__ float sigmoidf_fast(float z) {
    return 1.0f / (1.0f + __expf(-z));
}

// 8 fp16 weights (one uint4, permuted) x matching 8 h values -> 2 fp32 accs
__device__ __forceinline__ void acc8(uint4 w, float4 ha, float4 hb,
                                     float& s0, float& s1)
{
    float2 f0 = __half22float2(*(__half2*)&w.x);
    float2 f1 = __half22float2(*(__half2*)&w.y);
    float2 f2 = __half22float2(*(__half2*)&w.z);
    float2 f3 = __half22float2(*(__half2*)&w.w);
    s0 = fmaf(f0.x, ha.x, s0); s1 = fmaf(f0.y, ha.y, s1);
    s0 = fmaf(f1.x, ha.z, s0); s1 = fmaf(f1.y, ha.w, s1);
    s0 = fmaf(f2.x, hb.x, s0); s1 = fmaf(f2.y, hb.y, s1);
    s0 = fmaf(f3.x, hb.z, s0); s1 = fmaf(f3.y, hb.w, s1);
}

// fused 3-matrix row-dot (permuted layout), depth-1 weight prefetch,
// FULL warp reduction at the end (this was the R3/R4 bug: it was missing).
__device__ __forceinline__ void dot3(const uint4* pu, const uint4* pr,
                                     const uint4* pc, const float4* h4,
                                     int lane, float& du, float& dr, float& dc)
{
    float su0 = 0.f, su1 = 0.f, sr0 = 0.f, sr1 = 0.f, sc0 = 0.f, sc1 = 0.f;
    int j = lane;
    uint4 wu = pu[j], wr = pr[j], wc = pc[j];
    #pragma unroll 5
    for (int k = 0; k < 15; ++k) {
        const int jn = j + 32;
        uint4 nu = pu[jn], nr = pr[jn], nc = pc[jn];
        float4 ha = h4[j];         // stride 16B -> conflict-free
        float4 hb = h4[512 + j];   // stride 16B -> conflict-free
        acc8(wu, ha, hb, su0, su1);
        acc8(wr, ha, hb, sr0, sr1);
        acc8(wc, ha, hb, sc0, sc1);
        wu = nu; wr = nr; wc = nc; j = jn;
    }
    float4 ha = h4[j];
    float4 hb = h4[512 + j];
    acc8(wu, ha, hb, su0, su1);
    acc8(wr, ha, hb, sr0, sr1);
    acc8(wc, ha, hb, sc0, sc1);

    float su = su0 + su1, sr = sr0 + sr1, sc = sc0 + sc1;
    #pragma unroll
    for (int o = 16; o; o >>= 1) {
        su += __shfl_down_sync(0xffffffffu, su, o);
        sr += __shfl_down_sync(0xffffffffu, sr, o);
        sc += __shfl_down_sync(0xffffffffu, sc, o);
    }
    du = su; dr = sr; dc = sc;     // valid on lane 0
}

// ---------------- persistent GRU kernel -------------------------------------
__global__ void __launch_bounds__(BLOCK, 1)
gru_persistent(const float* __restrict__ x_seq,
               const float* __restrict__ uwx, const float* __restrict__ ub,
               const float* __restrict__ rwx, const float* __restrict__ rb,
               const float* __restrict__ wx,  const float* __restrict__ bb,
               const float* __restrict__ v,   const float* __restrict__ cc,
               float* __restrict__ out, int horizon, int ncache)
{
    extern __shared__ char smem[];
    float* h_s = (float*)smem;                         // 16 KB (always present)
    uint4* ws  = (uint4*)(smem + H * sizeof(float));   // ncache rows of U

    __shared__ float au_s[32], ar_s[32], aw_s[32];
    __shared__ float red_s[32];
    __shared__ float x_s;

    const int tid  = threadIdx.x;
    const int b    = blockIdx.x;
    const int G    = gridDim.x;
    const int warp = tid >> 5;
    const int lane = tid & 31;

    const int r0 = (int)(((long long)b       * H) / G);
    const int r1 = (int)(((long long)(b + 1) * H) / G);
    const int nrows = r1 - r0;   // 27 or 28

    // hoisted per-row gate constants (thread tid owns row r0+tid)
    float p_uwx = 0.f, p_ub = 0.f, p_rwx = 0.f, p_rb = 0.f;
    float p_wx = 0.f, p_bb = 0.f, p_v = 0.f;
    if (tid < nrows) {
        const int row = r0 + tid;
        p_uwx = uwx[row]; p_ub = ub[row];
        p_rwx = rwx[row]; p_rb = rb[row];
        p_wx  = wx[row];  p_bb = bb[row];
        p_v   = v[row];
    }

    // prologue: pin first `ncache` U-rows of this CTA into SMEM (verbatim copy,
    // layout-agnostic)
    {
        const uint4* src = ((const uint4*)g_wu) + (size_t)r0 * ROW_U4;
        const int n = ncache * ROW_U4;
        for (int i = tid; i < n; i += BLOCK) ws[i] = src[i];
    }

    // matvec row pointers (warp w owns row r0+w for all three matrices)
    const bool mv_active = (warp < nrows);
    const uint4* pu = nullptr; const uint4* pr = nullptr; const uint4* pc = nullptr;
    if (mv_active) {
        const size_t off = (size_t)(r0 + warp) * ROW_U4;
        pu = (warp < ncache) ? (ws + (size_t)warp * ROW_U4)
                             : (((const uint4*)g_wu) + off);
        pr = ((const uint4*)g_wr) + off;
        pc = ((const uint4*)g_wc) + off;
    }

    const float c0 = cc[0];
    unsigned phase = 0;
    const int total_steps = T_TRAIN + horizon;

    for (int t = 0; t < total_steps; ++t) {
        const int par = t & 1;
        const float* hin  = g_h[par];
        float*       hout = g_h[par ^ 1];

        // x for this step (deterministic: thread 0 re-sums partials)
        if (tid == 0) {
            float x;
            if (t < T_TRAIN) {
                x = x_seq[t];
            } else {
                const float* p = g_vhp[t - T_TRAIN];
                float s = 0.f;
                for (int i = 0; i < G; ++i) s += p[i];
                x = s + c0;
            }
            x_s = x;
        }

        // stage h into SMEM (1024 threads x 1 float4)
        {
            const float4* hin4 = (const float4*)hin;
            float4*       hs4  = (float4*)h_s;
            #pragma unroll
            for (int i = tid; i < H / 4; i += BLOCK) hs4[i] = hin4[i];
        }
        __syncthreads();
        const float x = x_s;

        // fused 3-matrix matvec, warp-per-row
        if (mv_active) {
            const float4* h4 = (const float4*)h_s;
            float du, dr, dc;
            dot3(pu, pr, pc, h4, lane, du, dr, dc);
            if (lane == 0) { au_s[warp] = du; ar_s[warp] = dr; aw_s[warp] = dc; }
        }
        __syncthreads();

        // gate math + h update
        const bool need_y = (t >= T_TRAIN - 1);
        if (tid < nrows) {
            const int row = r0 + tid;
            const float h_old = h_s[row];
            const float u  = sigmoidf_fast(p_uwx * x + au_s[tid] + p_ub);
            const float r  = sigmoidf_fast(p_rwx * x + ar_s[tid] + p_rb);
            const float hh = tanhf(p_wx * x + r * aw_s[tid] + p_bb);
            const float hn = h_old + u * (hh - h_old);
            hout[row] = hn;
            red_s[tid] = need_y ? p_v * hn : 0.f;
        }
        __syncthreads();
        if (need_y && tid == 0) {
            float s = 0.f;
            for (int i = 0; i < nrows; ++i) s += red_s[i];
            g_vhp[t - (T_TRAIN - 1)][b] = s;
        }

        grid_barrier(phase, G);
    }

    // emit predictions (deterministic final reduction)
    if (b == 0 && tid < horizon) {
        const float* p = g_vhp[tid + 1];
        float s = 0.f;
        for (int i = 0; i < G; ++i) s += p[i];
        out[tid] = s + c0;
    }
}

// ---------------- launch ----------------------------------------------------
extern "C" void kernel_launch(void* const* d_in, const int* in_sizes, int n_in,
                              void* d_out, int out_size)
{
    (void)in_sizes; (void)n_in;
    const float* x_seq = (const float*)d_in[0];
    // d_in[1] is the scalar 'horizon' (int32); we use out_size instead.
    const float* uwx = (const float*)d_in[2];
    const float* uWh = (const float*)d_in[3];
    const float* ub  = (const float*)d_in[4];
    const float* rwx = (const float*)d_in[5];
    const float* rWh = (const float*)d_in[6];
    const float* rb  = (const float*)d_in[7];
    const float* wx  = (const float*)d_in[8];
    const float* Wh  = (const float*)d_in[9];
    const float* bb  = (const float*)d_in[10];
    const float* v   = (const float*)d_in[11];
    const float* cc  = (const float*)d_in[12];

    int horizon = out_size;
    if (horizon > HMAX) horizon = HMAX;

    // reset persistent state (graph-capturable, deterministic per replay)
    void* p;
    cudaGetSymbolAddress(&p, g_h);     cudaMemsetAsync(p, 0, sizeof(float) * 2 * H);
    cudaGetSymbolAddress(&p, g_count); cudaMemsetAsync(p, 0, sizeof(unsigned));
    cudaGetSymbolAddress(&p, g_phase); cudaMemsetAsync(p, 0, sizeof(unsigned));

    // fp32 -> fp16 permuted weight conversion
    {
        const int total = H * ROW_U4;
        convert_w<<<(total + 255) / 256, 256>>>(uWh, rWh, Wh);
    }

    // big-smem path with deterministic fallback (same decision every call)
    const int dyn_big   = H * (int)sizeof(float) + NCACHE * ROW_U4 * (int)sizeof(uint4);
    const int dyn_small = H * (int)sizeof(float);
    int ncache = NCACHE;
    int dyn    = dyn_big;
    cudaError_t e = cudaFuncSetAttribute(gru_persistent,
                                         cudaFuncAttributeMaxDynamicSharedMemorySize,
                                         dyn_big);
    if (e != cudaSuccess) {
        (void)cudaGetLastError();   // clear non-sticky error
        ncache = 0;
        dyn    = dyn_small;
    }

    gru_persistent<<<GRID, BLOCK, dyn>>>(x_seq,
                                         uwx, ub,
                                         rwx, rb,
                                         wx,  bb,
                                         v,   cc,
                                         (float*)d_out, horizon, ncache);
}

// round 7
// speedup vs baseline: 4.0468x; 1.0154x over previous
#include <cuda_runtime.h>
#include <cuda_fp16.h>
#include <cstdint>

#define H        4096
#define T_TRAIN  2048
#define GRID     148
#define BLOCK    896          // 28 warps = max rows per CTA; reg cap 72/thread
#define HMAX     64
#define NCACHE   26           // U-matrix rows cached in SMEM per CTA (big path)
#define ROW_U4   512          // uint4 per weight row (4096 halves = 8 KB)

// ---------------- persistent device state ----------------------------------
__device__ __half   g_wu[(size_t)H * H];   // fp16 weights, PERMUTED layout:
__device__ __half   g_wr[(size_t)H * H];   // chunk j = cols {4j..4j+3, 2048+4j..2048+4j+3}
__device__ __half   g_wc[(size_t)H * H];
__device__ float    g_h[2][H];
__device__ float    g_vhp[HMAX + 1][GRID];
__device__ unsigned g_count;
__device__ unsigned g_phase;

// ---------------- fp32 -> fp16 conversion with column permutation -----------
__global__ void convert_w(const float* __restrict__ u,
                          const float* __restrict__ r,
                          const float* __restrict__ c)
{
    const int total = H * ROW_U4;
    int idx = blockIdx.x * blockDim.x + threadIdx.x;
    if (idx >= total) return;
    const int row = idx >> 9;
    const int j   = idx & 511;
    const int i0  = row * (H / 4) + j;        // float4 index of cols 4j..4j+3
    const int i1  = i0 + 512;                 // float4 index of cols 2048+4j..+3

    #define CVT_ONE(SRC, DST)                                           \
    {                                                                   \
        float4 a = ((const float4*)SRC)[i0];                            \
        float4 b = ((const float4*)SRC)[i1];                            \
        uint4 o;                                                        \
        __half2 t;                                                      \
        t = __floats2half2_rn(a.x, a.y); o.x = *(unsigned*)&t;          \
        t = __floats2half2_rn(a.z, a.w); o.y = *(unsigned*)&t;          \
        t = __floats2half2_rn(b.x, b.y); o.z = *(unsigned*)&t;          \
        t = __floats2half2_rn(b.z, b.w); o.w = *(unsigned*)&t;          \
        ((uint4*)DST)[idx] = o;                                         \
    }
    CVT_ONE(u, g_wu)
    CVT_ONE(r, g_wr)
    CVT_ONE(c, g_wc)
    #undef CVT_ONE
}

// ---------------- grid-wide barrier (single co-resident wave) ---------------
__device__ __forceinline__ void grid_barrier(unsigned &local_phase, int G) {
    __threadfence();
    __syncthreads();
    if (threadIdx.x == 0) {
        unsigned target = local_phase + 1;
        unsigned arrived = atomicAdd(&g_count, 1u) + 1;
        if (arrived == (unsigned)G) {
            atomicExch(&g_count, 0u);
            __threadfence();
            atomicAdd(&g_phase, 1u);
        } else {
            volatile unsigned* ph = &g_phase;
            while (*ph < target) { }
        }
    }
    local_phase++;
    __syncthreads();
    __threadfence();
}

__device__ __forceinline__ float sigmoidf_fast(float z) {
    return 1.0f / (1.0f + __expf(-z));
}

// packed f32x2 fma: acc(lo,hi) += (x0,x1) * (y0,y1); acc carried as u64
__device__ __forceinline__ void ffma2(unsigned long long& acc,
                                      float x0, float x1,
                                      float y0, float y1)
{
    unsigned long long a, b;
    asm("mov.b64 %0, {%1, %2};" : "=l"(a) : "f"(x0), "f"(x1));
    asm("mov.b64 %0, {%1, %2};" : "=l"(b) : "f"(y0), "f"(y1));
    asm("fma.rn.f32x2 %0, %1, %2, %3;" : "=l"(acc) : "l"(a), "l"(b), "l"(acc));
}

__device__ __forceinline__ float hsum2(unsigned long long acc) {
    float lo, hi;
    asm("mov.b64 {%0, %1}, %2;" : "=f"(lo), "=f"(hi) : "l"(acc));
    return lo + hi;
}

// 8 fp16 weights (one uint4, permuted) x matching 8 h values -> packed acc
__device__ __forceinline__ void acc8p(uint4 w, float4 ha, float4 hb,
                                      unsigned long long& acc)
{
    float2 f0 = __half22float2(*(__half2*)&w.x);
    float2 f1 = __half22float2(*(__half2*)&w.y);
    float2 f2 = __half22float2(*(__half2*)&w.z);
    float2 f3 = __half22float2(*(__half2*)&w.w);
    ffma2(acc, f0.x, f0.y, ha.x, ha.y);
    ffma2(acc, f1.x, f1.y, ha.z, ha.w);
    ffma2(acc, f2.x, f2.y, hb.x, hb.y);
    ffma2(acc, f3.x, f3.y, hb.z, hb.w);
}

// fused 3-matrix row-dot (permuted layout), depth-1 prefetch, first batch
// passed in (loop-invariant across time steps), full warp reduction.
__device__ __forceinline__ void dot3(const uint4* pu, const uint4* pr,
                                     const uint4* pc, const float4* h4,
                                     int lane,
                                     uint4 wu, uint4 wr, uint4 wc,
                                     float& du, float& dr, float& dc)
{
    unsigned long long au = 0ull, ar = 0ull, ac = 0ull;
    int j = lane;
    #pragma unroll 5
    for (int k = 0; k < 15; ++k) {
        const int jn = j + 32;
        uint4 nu = pu[jn], nr = pr[jn], nc = pc[jn];
        float4 ha = h4[j];         // stride 16B -> conflict-free
        float4 hb = h4[512 + j];   // stride 16B -> conflict-free
        acc8p(wu, ha, hb, au);
        acc8p(wr, ha, hb, ar);
        acc8p(wc, ha, hb, ac);
        wu = nu; wr = nr; wc = nc; j = jn;
    }
    float4 ha = h4[j];
    float4 hb = h4[512 + j];
    acc8p(wu, ha, hb, au);
    acc8p(wr, ha, hb, ar);
    acc8p(wc, ha, hb, ac);

    float su = hsum2(au), sr = hsum2(ar), sc = hsum2(ac);
    #pragma unroll
    for (int o = 16; o; o >>= 1) {
        su += __shfl_down_sync(0xffffffffu, su, o);
        sr += __shfl_down_sync(0xffffffffu, sr, o);
        sc += __shfl_down_sync(0xffffffffu, sc, o);
    }
    du = su; dr = sr; dc = sc;     // valid on lane 0
}

// ---------------- persistent GRU kernel -------------------------------------
__global__ void __launch_bounds__(BLOCK, 1)
gru_persistent(const float* __restrict__ x_seq,
               const float* __restrict__ uwx, const float* __restrict__ ub,
               const float* __restrict__ rwx, const float* __restrict__ rb,
               const float* __restrict__ wx,  const float* __restrict__ bb,
               const float* __restrict__ v,   const float* __restrict__ cc,
               float* __restrict__ out, int horizon, int ncache)
{
    extern __shared__ char smem[];
    float* h_s = (float*)smem;                         // 16 KB
    uint4* ws  = (uint4*)(smem + H * sizeof(float));   // ncache rows of U

    __shared__ float au_s[32], ar_s[32], aw_s[32];

    const int tid  = threadIdx.x;
    const int b    = blockIdx.x;
    const int G    = gridDim.x;
    const int warp = tid >> 5;
    const int lane = tid & 31;

    const int r0 = (int)(((long long)b       * H) / G);
    const int r1 = (int)(((long long)(b + 1) * H) / G);
    const int nrows = r1 - r0;   // 27 or 28 (<= 28 = warps available)

    // per-row gate constants: lane L of warp 0 owns row r0+L
    float p_uwx = 0.f, p_ub = 0.f, p_rwx = 0.f, p_rb = 0.f;
    float p_wx = 0.f, p_bb = 0.f, p_v = 0.f;
    if (warp == 0 && lane < nrows) {
        const int row = r0 + lane;
        p_uwx = uwx[row]; p_ub = ub[row];
        p_rwx = rwx[row]; p_rb = rb[row];
        p_wx  = wx[row];  p_bb = bb[row];
        p_v   = v[row];
    }

    // prologue: pin first `ncache` U-rows of this CTA into SMEM
    {
        const uint4* src = ((const uint4*)g_wu) + (size_t)r0 * ROW_U4;
        const int n = ncache * ROW_U4;
        for (int i = tid; i < n; i += BLOCK) ws[i] = src[i];
    }
    __syncthreads();   // ws ready before warps 0..ncache-1 preload from it

    // matvec row pointers (warp w owns row r0+w for all three matrices)
    const bool mv_active = (warp < nrows);
    const uint4* pu = nullptr; const uint4* pr = nullptr; const uint4* pc = nullptr;
    uint4 wu0 = {0,0,0,0}, wr0 = {0,0,0,0}, wc0 = {0,0,0,0};
    if (mv_active) {
        const size_t off = (size_t)(r0 + warp) * ROW_U4;
        pu = (warp < ncache) ? (ws + (size_t)warp * ROW_U4)
                             : (((const uint4*)g_wu) + off);
        pr = ((const uint4*)g_wr) + off;
        pc = ((const uint4*)g_wc) + off;
        // loop-invariant first batch, held in registers for all steps
        wu0 = pu[lane]; wr0 = pr[lane]; wc0 = pc[lane];
    }

    const float c0 = cc[0];
    unsigned phase = 0;
    const int total_steps = T_TRAIN + horizon;

    for (int t = 0; t < total_steps; ++t) {
        const int par = t & 1;
        const float* hin  = g_h[par];
        float*       hout = g_h[par ^ 1];

        // x for this step: warp 0 computes it in registers (bfly -> all lanes)
        float x = 0.f;
        if (warp == 0) {
            if (t < T_TRAIN) {
                x = x_seq[t];
            } else {
                const float* p = g_vhp[t - T_TRAIN];
                float s = 0.f;
                for (int i = lane; i < G; i += 32) s += p[i];
                #pragma unroll
                for (int o = 16; o; o >>= 1)
                    s += __shfl_xor_sync(0xffffffffu, s, o);
                x = s + c0;
            }
        }

        // stage h into SMEM
        {
            const float4* hin4 = (const float4*)hin;
            float4*       hs4  = (float4*)h_s;
            #pragma unroll
            for (int i = tid; i < H / 4; i += BLOCK) hs4[i] = hin4[i];
        }
        __syncthreads();

        // fused 3-matrix matvec, warp-per-row
        if (mv_active) {
            const float4* h4 = (const float4*)h_s;
            float du, dr, dc;
            dot3(pu, pr, pc, h4, lane, wu0, wr0, wc0, du, dr, dc);
            if (lane == 0) { au_s[warp] = du; ar_s[warp] = dr; aw_s[warp] = dc; }
        }
        __syncthreads();

        // gate math + h update + y partial: all inside warp 0
        const bool need_y = (t >= T_TRAIN - 1);
        if (warp == 0) {
            float yv = 0.f;
            if (lane < nrows) {
                const int row = r0 + lane;
                const float h_old = h_s[row];
                const float u  = sigmoidf_fast(p_uwx * x + au_s[lane] + p_ub);
                const float r  = sigmoidf_fast(p_rwx * x + ar_s[lane] + p_rb);
                const float hh = tanhf(p_wx * x + r * aw_s[lane] + p_bb);
                const float hn = h_old + u * (hh - h_old);
                hout[row] = hn;
                yv = need_y ? p_v * hn : 0.f;
            }
            if (need_y) {
                #pragma unroll
                for (int o = 16; o; o >>= 1)
                    yv += __shfl_down_sync(0xffffffffu, yv, o);
                if (lane == 0) g_vhp[t - (T_TRAIN - 1)][b] = yv;
            }
        }

        grid_barrier(phase, G);
    }

    // emit predictions (deterministic final reduction)
    if (b == 0 && tid < horizon) {
        const float* p = g_vhp[tid + 1];
        float s = 0.f;
        for (int i = 0; i < G; ++i) s += p[i];
        out[tid] = s + c0;
    }
}

// ---------------- launch ----------------------------------------------------
extern "C" void kernel_launch(void* const* d_in, const int* in_sizes, int n_in,
                              void* d_out, int out_size)
{
    (void)in_sizes; (void)n_in;
    const float* x_seq = (const float*)d_in[0];
    // d_in[1] is the scalar 'horizon' (int32); we use out_size instead.
    const float* uwx = (const float*)d_in[2];
    const float* uWh = (const float*)d_in[3];
    const float* ub  = (const float*)d_in[4];
    const float* rwx = (const float*)d_in[5];
    const float* rWh = (const float*)d_in[6];
    const float* rb  = (const float*)d_in[7];
    const float* wx  = (const float*)d_in[8];
    const float* Wh  = (const float*)d_in[9];
    const float* bb  = (const float*)d_in[10];
    const float* v   = (const float*)d_in[11];
    const float* cc  = (const float*)d_in[12];

    int horizon = out_size;
    if (horizon > HMAX) horizon = HMAX;

    // reset persistent state (graph-capturable, deterministic per replay)
    void* p;
    cudaGetSymbolAddress(&p, g_h);     cudaMemsetAsync(p, 0, sizeof(float) * 2 * H);
    cudaGetSymbolAddress(&p, g_count); cudaMemsetAsync(p, 0, sizeof(unsigned));
    cudaGetSymbolAddress(&p, g_phase); cudaMemsetAsync(p, 0, sizeof(unsigned));

    // fp32 -> fp16 permuted weight conversion
    {
        const int total = H * ROW_U4;
        convert_w<<<(total + 255) / 256, 256>>>(uWh, rWh, Wh);
    }

    // dyn-smem: try 26-row cache, then 25, then none (same decision every call)
    const int base = H * (int)sizeof(float);
    int ncache = NCACHE;
    int dyn    = base + NCACHE * ROW_U4 * (int)sizeof(uint4);
    cudaError_t e = cudaFuncSetAttribute(gru_persistent,
                                         cudaFuncAttributeMaxDynamicSharedMemorySize,
                                         dyn);
    if (e != cudaSuccess) {
        (void)cudaGetLastError();
        ncache = 25;
        dyn    = base + 25 * ROW_U4 * (int)sizeof(uint4);
        e = cudaFuncSetAttribute(gru_persistent,
                                 cudaFuncAttributeMaxDynamicSharedMemorySize,
                                 dyn);
        if (e != cudaSuccess) {
            (void)cudaGetLastError();
            ncache = 0;
            dyn    = base;
        }
    }

    gru_persistent<<<GRID, BLOCK, dyn>>>(x_seq,
                                         uwx, ub,
                                         rwx, rb,
                                         wx,  bb,
                                         v,   cc,
                                         (float*)d_out, horizon, ncache);
}

// round 8
// speedup vs baseline: 4.1519x; 1.0260x over previous
#include <cuda_runtime.h>
#include <cuda_fp16.h>
#include <cstdint>

#define H        4096
#define T_TRAIN  2048
#define GRID     148
#define BLOCK    1024         // 28 dot warps + 4 stager warps
#define DOTW     28
#define HMAX     64
#define NCACHE   26           // U-matrix rows cached in SMEM per CTA (big path)
#define ROW_U4   512          // uint4 per weight row (4096 halves = 8 KB)

// ---------------- persistent device state ----------------------------------
__device__ __half   g_wu[(size_t)H * H];   // fp16 weights, PERMUTED layout:
__device__ __half   g_wr[(size_t)H * H];   // chunk j = cols {4j..4j+3, 2048+4j..2048+4j+3}
__device__ __half   g_wc[(size_t)H * H];
__device__ float    g_h[2][H];
__device__ float    g_vhp[HMAX + 1][GRID];
__device__ unsigned g_count;
__device__ unsigned g_phase;

// ---------------- fp32 -> fp16 conversion with column permutation -----------
__global__ void convert_w(const float* __restrict__ u,
                          const float* __restrict__ r,
                          const float* __restrict__ c)
{
    const int total = H * ROW_U4;
    int idx = blockIdx.x * blockDim.x + threadIdx.x;
    if (idx >= total) return;
    const int row = idx >> 9;
    const int j   = idx & 511;
    const int i0  = row * (H / 4) + j;        // float4 index of cols 4j..4j+3
    const int i1  = i0 + 512;                 // float4 index of cols 2048+4j..+3

    #define CVT_ONE(SRC, DST)                                           \
    {                                                                   \
        float4 a = ((const float4*)SRC)[i0];                            \
        float4 b = ((const float4*)SRC)[i1];                            \
        uint4 o;                                                        \
        __half2 t;                                                      \
        t = __floats2half2_rn(a.x, a.y); o.x = *(unsigned*)&t;          \
        t = __floats2half2_rn(a.z, a.w); o.y = *(unsigned*)&t;          \
        t = __floats2half2_rn(b.x, b.y); o.z = *(unsigned*)&t;          \
        t = __floats2half2_rn(b.z, b.w); o.w = *(unsigned*)&t;          \
        ((uint4*)DST)[idx] = o;                                         \
    }
    CVT_ONE(u, g_wu)
    CVT_ONE(r, g_wr)
    CVT_ONE(c, g_wc)
    #undef CVT_ONE
}

// ---------------- grid-wide barrier (single co-resident wave) ---------------
__device__ __forceinline__ void grid_barrier(unsigned &local_phase, int G) {
    __threadfence();
    __syncthreads();
    if (threadIdx.x == 0) {
        unsigned target = local_phase + 1;
        unsigned arrived = atomicAdd(&g_count, 1u) + 1;
        if (arrived == (unsigned)G) {
            atomicExch(&g_count, 0u);
            __threadfence();
            atomicAdd(&g_phase, 1u);
        } else {
            volatile unsigned* ph = &g_phase;
            while (*ph < target) { }
        }
    }
    local_phase++;
    __syncthreads();
    __threadfence();
}

__device__ __forceinline__ float sigmoidf_fast(float z) {
    return 1.0f / (1.0f + __expf(-z));
}

// packed f32x2 fma: acc(lo,hi) += (x0,x1) * (y0,y1); acc carried as u64
__device__ __forceinline__ void ffma2(unsigned long long& acc,
                                      float x0, float x1,
                                      float y0, float y1)
{
    unsigned long long a, b;
    asm("mov.b64 %0, {%1, %2};" : "=l"(a) : "f"(x0), "f"(x1));
    asm("mov.b64 %0, {%1, %2};" : "=l"(b) : "f"(y0), "f"(y1));
    asm("fma.rn.f32x2 %0, %1, %2, %3;" : "=l"(acc) : "l"(a), "l"(b), "l"(acc));
}

__device__ __forceinline__ float hsum2(unsigned long long acc) {
    float lo, hi;
    asm("mov.b64 {%0, %1}, %2;" : "=f"(lo), "=f"(hi) : "l"(acc));
    return lo + hi;
}

// 8 fp16 weights (one uint4, permuted) x matching 8 h values -> packed acc
__device__ __forceinline__ void acc8p(uint4 w, float4 ha, float4 hb,
                                      unsigned long long& acc)
{
    float2 f0 = __half22float2(*(__half2*)&w.x);
    float2 f1 = __half22float2(*(__half2*)&w.y);
    float2 f2 = __half22float2(*(__half2*)&w.z);
    float2 f3 = __half22float2(*(__half2*)&w.w);
    ffma2(acc, f0.x, f0.y, ha.x, ha.y);
    ffma2(acc, f1.x, f1.y, ha.z, ha.w);
    ffma2(acc, f2.x, f2.y, hb.x, hb.y);
    ffma2(acc, f3.x, f3.y, hb.z, hb.w);
}

// spin on 4 per-stager-warp step flags (values are monotone step numbers)
__device__ __forceinline__ void wait_flags(volatile int* f, int t) {
    while (f[0] < t || f[1] < t || f[2] < t || f[3] < t) { }
}

// 8 dot batches (j = lane + 32k, k in [k0, k0+8)), depth-1 weight prefetch
__device__ __forceinline__ void dot3_half(const uint4* pu, const uint4* pr,
                                          const uint4* pc, const float4* h4,
                                          int lane, int k0,
                                          unsigned long long& au,
                                          unsigned long long& ar,
                                          unsigned long long& ac)
{
    int j = lane + 32 * k0;
    uint4 wu = pu[j], wr = pr[j], wc = pc[j];
    #pragma unroll 7
    for (int k = 0; k < 7; ++k) {
        const int jn = j + 32;
        uint4 nu = pu[jn], nr = pr[jn], nc = pc[jn];
        float4 ha = h4[j];         // stride 16B -> conflict-free
        float4 hb = h4[512 + j];   // stride 16B -> conflict-free
        acc8p(wu, ha, hb, au);
        acc8p(wr, ha, hb, ar);
        acc8p(wc, ha, hb, ac);
        wu = nu; wr = nr; wc = nc; j = jn;
    }
    float4 ha = h4[j];
    float4 hb = h4[512 + j];
    acc8p(wu, ha, hb, au);
    acc8p(wr, ha, hb, ar);
    acc8p(wc, ha, hb, ac);
}

// ---------------- persistent GRU kernel -------------------------------------
__global__ void __launch_bounds__(BLOCK, 1)
gru_persistent(const float* __restrict__ x_seq,
               const float* __restrict__ uwx, const float* __restrict__ ub,
               const float* __restrict__ rwx, const float* __restrict__ rb,
               const float* __restrict__ wx,  const float* __restrict__ bb,
               const float* __restrict__ v,   const float* __restrict__ cc,
               float* __restrict__ out, int horizon, int ncache)
{
    extern __shared__ char smem[];
    float* h_s = (float*)smem;                         // 16 KB
    uint4* ws  = (uint4*)(smem + H * sizeof(float));   // ncache rows of U

    __shared__ float au_s[32], ar_s[32], aw_s[32];
    __shared__ float x_s;
    __shared__ int   flA[4], flB[4];                   // per-stager-warp flags

    const int tid  = threadIdx.x;
    const int b    = blockIdx.x;
    const int G    = gridDim.x;
    const int warp = tid >> 5;
    const int lane = tid & 31;

    const int r0 = (int)(((long long)b       * H) / G);
    const int r1 = (int)(((long long)(b + 1) * H) / G);
    const int nrows = r1 - r0;   // 27 or 28 (<= DOTW)

    if (tid < 4) { flA[tid] = -1; flB[tid] = -1; }

    // per-row gate constants: lane L of warp 0 owns row r0+L
    float p_uwx = 0.f, p_ub = 0.f, p_rwx = 0.f, p_rb = 0.f;
    float p_wx = 0.f, p_bb = 0.f, p_v = 0.f;
    if (warp == 0 && lane < nrows) {
        const int row = r0 + lane;
        p_uwx = uwx[row]; p_ub = ub[row];
        p_rwx = rwx[row]; p_rb = rb[row];
        p_wx  = wx[row];  p_bb = bb[row];
        p_v   = v[row];
    }

    // prologue: pin first `ncache` U-rows of this CTA into SMEM
    {
        const uint4* src = ((const uint4*)g_wu) + (size_t)r0 * ROW_U4;
        const int n = ncache * ROW_U4;
        for (int i = tid; i < n; i += BLOCK) ws[i] = src[i];
    }

    // matvec row pointers (warp w owns row r0+w for all three matrices)
    const bool mv_active = (warp < nrows);
    const uint4* pu = nullptr; const uint4* pr = nullptr; const uint4* pc = nullptr;
    if (mv_active) {
        const size_t off = (size_t)(r0 + warp) * ROW_U4;
        pu = (warp < ncache) ? (ws + (size_t)warp * ROW_U4)
                             : (((const uint4*)g_wu) + off);
        pr = ((const uint4*)g_wr) + off;
        pc = ((const uint4*)g_wc) + off;
    }

    const float c0 = cc[0];
    unsigned phase = 0;
    const int total_steps = T_TRAIN + horizon;
    __syncthreads();   // flags init + ws cache visible to all warps

    for (int t = 0; t < total_steps; ++t) {
        const int par = t & 1;
        const float* hin  = g_h[par];
        float*       hout = g_h[par ^ 1];

        if (warp >= DOTW) {
            // ---- stager warps: copy h in 2 chunks, publish step flags ----
            const int sw  = warp - DOTW;        // 0..3
            const int sid = tid - DOTW * 32;    // 0..127
            const float4* src = (const float4*)hin;
            float4*       dst = (float4*)h_s;
            // chunk A: f4 [0,256) and [512,768)  (dot batches k<8)
            #pragma unroll
            for (int i = sid; i < 256; i += 128) {
                dst[i]       = src[i];
                dst[512 + i] = src[512 + i];
            }
            __syncwarp();
            __threadfence_block();
            if (lane == 0) flA[sw] = t;
            // chunk B: f4 [256,512) and [768,1024)  (dot batches k>=8)
            #pragma unroll
            for (int i = sid; i < 256; i += 128) {
                dst[256 + i] = src[256 + i];
                dst[768 + i] = src[768 + i];
            }
            __syncwarp();
            __threadfence_block();
            if (lane == 0) flB[sw] = t;

            // warp 31 additionally computes x for this step (hidden latency)
            if (warp == 31) {
                if (t < T_TRAIN) {
                    if (lane == 0) x_s = x_seq[t];
                } else {
                    const float* p = g_vhp[t - T_TRAIN];
                    float s = 0.f;
                    for (int i = lane; i < G; i += 32) s += p[i];
                    #pragma unroll
                    for (int o = 16; o; o >>= 1)
                        s += __shfl_down_sync(0xffffffffu, s, o);
                    if (lane == 0) x_s = s + c0;
                }
            }
        } else if (mv_active) {
            // ---- dot warps: fused 3-matrix row-dot, flag-gated on h chunks ----
            const float4* h4 = (const float4*)h_s;
            unsigned long long au = 0ull, ar = 0ull, ac = 0ull;
            wait_flags(flA, t);
            dot3_half(pu, pr, pc, h4, lane, 0, au, ar, ac);
            wait_flags(flB, t);
            dot3_half(pu, pr, pc, h4, lane, 8, au, ar, ac);

            float su = hsum2(au), sr = hsum2(ar), sc = hsum2(ac);
            #pragma unroll
            for (int o = 16; o; o >>= 1) {
                su += __shfl_down_sync(0xffffffffu, su, o);
                sr += __shfl_down_sync(0xffffffffu, sr, o);
                sc += __shfl_down_sync(0xffffffffu, sc, o);
            }
            if (lane == 0) { au_s[warp] = su; ar_s[warp] = sr; aw_s[warp] = sc; }
        }
        __syncthreads();   // dots + x_s + full h_s ready

        // gate math + h update + y partial: warp 0
        const bool need_y = (t >= T_TRAIN - 1);
        if (warp == 0) {
            const float x = x_s;
            float yv = 0.f;
            if (lane < nrows) {
                const int row = r0 + lane;
                const float h_old = h_s[row];
                const float u  = sigmoidf_fast(p_uwx * x + au_s[lane] + p_ub);
                const float r  = sigmoidf_fast(p_rwx * x + ar_s[lane] + p_rb);
                const float hh = tanhf(p_wx * x + r * aw_s[lane] + p_bb);
                const float hn = h_old + u * (hh - h_old);
                hout[row] = hn;
                yv = need_y ? p_v * hn : 0.f;
            }
            if (need_y) {
                #pragma unroll
                for (int o = 16; o; o >>= 1)
                    yv += __shfl_down_sync(0xffffffffu, yv, o);
                if (lane == 0) g_vhp[t - (T_TRAIN - 1)][b] = yv;
            }
        }

        grid_barrier(phase, G);
    }

    // emit predictions (deterministic final reduction)
    if (b == 0 && tid < horizon) {
        const float* p = g_vhp[tid + 1];
        float s = 0.f;
        for (int i = 0; i < G; ++i) s += p[i];
        out[tid] = s + c0;
    }
}

// ---------------- launch ----------------------------------------------------
extern "C" void kernel_launch(void* const* d_in, const int* in_sizes, int n_in,
                              void* d_out, int out_size)
{
    (void)in_sizes; (void)n_in;
    const float* x_seq = (const float*)d_in[0];
    // d_in[1] is the scalar 'horizon' (int32); we use out_size instead.
    const float* uwx = (const float*)d_in[2];
    const float* uWh = (const float*)d_in[3];
    const float* ub  = (const float*)d_in[4];
    const float* rwx = (const float*)d_in[5];
    const float* rWh = (const float*)d_in[6];
    const float* rb  = (const float*)d_in[7];
    const float* wx  = (const float*)d_in[8];
    const float* Wh  = (const float*)d_in[9];
    const float* bb  = (const float*)d_in[10];
    const float* v   = (const float*)d_in[11];
    const float* cc  = (const float*)d_in[12];

    int horizon = out_size;
    if (horizon > HMAX) horizon = HMAX;

    // reset persistent state (graph-capturable, deterministic per replay)
    void* p;
    cudaGetSymbolAddress(&p, g_h);     cudaMemsetAsync(p, 0, sizeof(float) * 2 * H);
    cudaGetSymbolAddress(&p, g_count); cudaMemsetAsync(p, 0, sizeof(unsigned));
    cudaGetSymbolAddress(&p, g_phase); cudaMemsetAsync(p, 0, sizeof(unsigned));

    // fp32 -> fp16 permuted weight conversion
    {
        const int total = H * ROW_U4;
        convert_w<<<(total + 255) / 256, 256>>>(uWh, rWh, Wh);
    }

    // dyn-smem: try 26-row cache, then 25, then none (same decision every call)
    const int base = H * (int)sizeof(float);
    int ncache = NCACHE;
    int dyn    = base + NCACHE * ROW_U4 * (int)sizeof(uint4);
    cudaError_t e = cudaFuncSetAttribute(gru_persistent,
                                         cudaFuncAttributeMaxDynamicSharedMemorySize,
                                         dyn);
    if (e != cudaSuccess) {
        (void)cudaGetLastError();
        ncache = 25;
        dyn    = base + 25 * ROW_U4 * (int)sizeof(uint4);
        e = cudaFuncSetAttribute(gru_persistent,
                                 cudaFuncAttributeMaxDynamicSharedMemorySize,
                                 dyn);
        if (e != cudaSuccess) {
            (void)cudaGetLastError();
            ncache = 0;
            dyn    = base;
        }
    }

    gru_persistent<<<GRID, BLOCK, dyn>>>(x_seq,
                                         uwx, ub,
                                         rwx, rb,
                                         wx,  bb,
                                         v,   cc,
                                         (float*)d_out, horizon, ncache);
}